// round 4
// baseline (speedup 1.0000x reference)
#include <cuda_runtime.h>

// Problem constants (K = 1024 boxes)
#define KBOX   1024
#define ROWS_I 1023                 // off-diag rows per i
#define NROWS  (KBOX * (KBOX - 1))  // 1,047,552
#define TM     128                  // rows per block tile
#define NTHREADS 256
#define S_H    130                  // sHT stride over m (even, ==2 mod 4)

// smem layout (floats)
#define OFF_W2  0                       // 128*128 = 16384
#define OFF_HT  16384                   // 128*S_H = 16640
#define OFF_F   (OFF_HT + 128 * S_H)    // 128*13  = 1664
#define OFF_W1  (OFF_F + 128 * 13)      // 13*128  = 1664
#define OFF_B1  (OFF_W1 + 13 * 128)     // 128
#define OFF_B2  (OFF_B1 + 128)          // 128
#define SMEM_FLOATS (OFF_B2 + 128)
#define SMEM_BYTES  (SMEM_FLOATS * 4)

// Packed dual-FMA: d = a*b + c on two fp32 lanes in one FFMA2 issue.
// ptxas will not auto-fuse this from C++; must come from PTX fma.rn.f32x2.
__device__ __forceinline__ float2 ffma2(float2 a, float2 b, float2 c) {
    float2 d;
    asm("fma.rn.f32x2 %0, %1, %2, %3;"
        : "=l"(*reinterpret_cast<unsigned long long*>(&d))
        : "l"(*reinterpret_cast<unsigned long long*>(&a)),
          "l"(*reinterpret_cast<unsigned long long*>(&b)),
          "l"(*reinterpret_cast<unsigned long long*>(&c)));
    return d;
}

__global__ void __launch_bounds__(NTHREADS, 1)
pair_mlp_kernel(const float* __restrict__ boxes,
                const float* __restrict__ W1,
                const float* __restrict__ b1,
                const float* __restrict__ W2,
                const float* __restrict__ b2,
                float* __restrict__ out)
{
    extern __shared__ float smem[];
    float* sW2 = smem + OFF_W2;   // [k][n] row-major, 128x128
    float* sHT = smem + OFF_HT;   // transposed h: sHT[k*S_H + m]
    float* sF  = smem + OFF_F;    // feats: sF[m*13 + kk]
    float* sW1 = smem + OFF_W1;   // [kk][n] row-major, 13x128
    float* sB1 = smem + OFF_B1;
    float* sB2 = smem + OFF_B2;

    const int t = threadIdx.x;

    // ---- Stage weights into smem (coalesced) ----
    #pragma unroll
    for (int idx = t; idx < 16384 / 4; idx += NTHREADS)
        reinterpret_cast<float4*>(sW2)[idx] = reinterpret_cast<const float4*>(W2)[idx];
    for (int idx = t; idx < 13 * 128; idx += NTHREADS)
        sW1[idx] = W1[idx];
    if (t < 128) { sB1[t] = b1[t]; sB2[t] = b2[t]; }

    // ---- Pair features: first 128 threads, one row each ----
    if (t < TM) {
        const long r = (long)blockIdx.x * TM + t;
        const int i = (int)(r / ROWS_I);
        const int p = (int)(r - (long)i * ROWS_I);
        const int j = (p < i) ? p : p + 1;

        const float4 bi = reinterpret_cast<const float4*>(boxes)[i];
        const float4 bj = reinterpret_cast<const float4*>(boxes)[j];
        const float xi = bi.x, yi = bi.y, wi = bi.z, hi = bi.w;
        const float xj = bj.x, yj = bj.y, wj = bj.z, hj = bj.w;

        const float dx = (xj - xi) / wi;
        const float dy = (yj - yi) / hi;
        const float dw = logf(wj / wi + 1e-6f);
        const float dh = logf(hj / hi + 1e-6f);
        const float iw = fmaxf(0.0f, fminf(xi + wi, xj + wj) - fmaxf(xi, xj));
        const float ih = fmaxf(0.0f, fminf(yi + hi, yj + hj) - fmaxf(yi, yj));
        const float inter = iw * ih;
        const float uni = wi * hi + wj * hj - inter;
        const float iou = inter / (uni + 1e-6f);

        float* f = sF + t * 13;
        f[0] = dx;  f[1] = dy;  f[2] = dw;  f[3] = dh;
        f[4] = wi;  f[5] = hi;  f[6] = wj;  f[7] = hj;
        f[8] = iou; f[9] = xi;  f[10] = yi; f[11] = xj; f[12] = yj;
    }
    __syncthreads();

    // ---- GEMM1 + relu: h[m][n] = relu(feats[m]@W1[:,n] + b1[n]) ----
    // Thread covers 4 consecutive n (lane-mapped) x 16 rows (warp-mapped).
    // W1 column hoisted into registers; feats reads are warp-broadcast LDS.
    {
        const int n4 = (t & 31) * 4;
        const int mh = t >> 5;        // warp id 0..7 -> 16 rows each

        float w1c[13][4];
        #pragma unroll
        for (int kk = 0; kk < 13; kk++) {
            const float4 v = *reinterpret_cast<const float4*>(&sW1[kk * 128 + n4]);
            w1c[kk][0] = v.x; w1c[kk][1] = v.y; w1c[kk][2] = v.z; w1c[kk][3] = v.w;
        }
        const float4 b1v = *reinterpret_cast<const float4*>(&sB1[n4]);

        #pragma unroll 2
        for (int mm = 0; mm < 16; mm++) {
            const int m = mh * 16 + mm;
            float a0 = b1v.x, a1 = b1v.y, a2 = b1v.z, a3 = b1v.w;
            const float* f = sF + m * 13;
            #pragma unroll
            for (int kk = 0; kk < 13; kk++) {
                const float fv = f[kk];   // broadcast within warp
                a0 = fmaf(fv, w1c[kk][0], a0);
                a1 = fmaf(fv, w1c[kk][1], a1);
                a2 = fmaf(fv, w1c[kk][2], a2);
                a3 = fmaf(fv, w1c[kk][3], a3);
            }
            sHT[(n4 + 0) * S_H + m] = fmaxf(a0, 0.0f);
            sHT[(n4 + 1) * S_H + m] = fmaxf(a1, 0.0f);
            sHT[(n4 + 2) * S_H + m] = fmaxf(a2, 0.0f);
            sHT[(n4 + 3) * S_H + m] = fmaxf(a3, 0.0f);
        }
    }
    __syncthreads();

    // ---- GEMM2: C[m][n] = h[m][:] @ W2 + b2, packed f32x2 along row pairs ----
    // Thread tile: 16 rows (as 8 float2 row-pairs) x 4 cols.
    const int tx = t & 31;        // lane -> n
    const int ty = t >> 5;        // warp -> m
    const int n0 = tx * 4;
    const int m0 = ty * 16;       // even -> 8B-aligned sHT pair loads

    float2 c[8][4];
    {
        const float4 bv = *reinterpret_cast<const float4*>(&sB2[n0]);
        #pragma unroll
        for (int mi = 0; mi < 8; mi++) {
            c[mi][0] = make_float2(bv.x, bv.x);
            c[mi][1] = make_float2(bv.y, bv.y);
            c[mi][2] = make_float2(bv.z, bv.z);
            c[mi][3] = make_float2(bv.w, bv.w);
        }
    }

    #pragma unroll 4
    for (int k = 0; k < 128; k++) {
        const float4 wv = *reinterpret_cast<const float4*>(&sW2[k * 128 + n0]);
        float2 a[8];
        const float* hrow = &sHT[k * S_H + m0];
        #pragma unroll
        for (int mi = 0; mi < 8; mi++)
            a[mi] = *reinterpret_cast<const float2*>(hrow + 2 * mi);  // warp-broadcast LDS.64

        const float2 w0 = make_float2(wv.x, wv.x);
        const float2 w1 = make_float2(wv.y, wv.y);
        const float2 w2 = make_float2(wv.z, wv.z);
        const float2 w3 = make_float2(wv.w, wv.w);
        #pragma unroll
        for (int mi = 0; mi < 8; mi++) {
            c[mi][0] = ffma2(a[mi], w0, c[mi][0]);
            c[mi][1] = ffma2(a[mi], w1, c[mi][1]);
            c[mi][2] = ffma2(a[mi], w2, c[mi][2]);
            c[mi][3] = ffma2(a[mi], w3, c[mi][3]);
        }
    }

    // ---- Epilogue: coalesced STG.128 ----
    float* outBase = out + ((size_t)blockIdx.x * TM + m0) * 128 + n0;
    #pragma unroll
    for (int mi = 0; mi < 8; mi++) {
        const float4 r0 = make_float4(c[mi][0].x, c[mi][1].x, c[mi][2].x, c[mi][3].x);
        const float4 r1 = make_float4(c[mi][0].y, c[mi][1].y, c[mi][2].y, c[mi][3].y);
        *reinterpret_cast<float4*>(outBase + (size_t)(2 * mi) * 128)     = r0;
        *reinterpret_cast<float4*>(outBase + (size_t)(2 * mi + 1) * 128) = r1;
    }
}

extern "C" void kernel_launch(void* const* d_in, const int* in_sizes, int n_in,
                              void* d_out, int out_size)
{
    const float* boxes = (const float*)d_in[0];
    const float* W1    = (const float*)d_in[1];
    const float* b1    = (const float*)d_in[2];
    const float* W2    = (const float*)d_in[3];
    const float* b2    = (const float*)d_in[4];
    float* out = (float*)d_out;

    // 146,432 bytes dynamic smem > 48KB default: opt in (idempotent, capture-safe)
    cudaFuncSetAttribute(pair_mlp_kernel,
                         cudaFuncAttributeMaxDynamicSharedMemorySize, SMEM_BYTES);

    const int grid = NROWS / TM;   // 8184, exact
    pair_mlp_kernel<<<grid, NTHREADS, SMEM_BYTES>>>(boxes, W1, b1, W2, b2, out);
}

// round 6
// speedup vs baseline: 1.3405x; 1.3405x over previous
#include <cuda_runtime.h>

// ---------------- Problem constants ----------------
#define KBOX   1024
#define ROWS_I 1023
#define NTILES 8184                  // 1,047,552 rows / 128
#define TM     128
#define NTHREADS 256
#define GRID   148                   // persistent, 1 CTA per SM
#define S_H    130                   // sHT row stride (floats), even

// smem layout (float offsets)
#define OFF_W2  0                    // 128x128
#define OFF_HT  16384                // 128 x S_H
#define OFF_FT  (OFF_HT + 128 * S_H) // 13 x 128, feats transposed
#define OFF_W1  (OFF_FT + 13 * 128)  // 13 x 128
#define SMEM_FLOATS (OFF_W1 + 13 * 128)
#define SMEM_BYTES  (SMEM_FLOATS * 4)    // 145,408 B

// Packed dual fp32 FMA — ptxas never auto-fuses this from C++.
__device__ __forceinline__ float2 ffma2(float2 a, float2 b, float2 c) {
    float2 d;
    asm("fma.rn.f32x2 %0, %1, %2, %3;"
        : "=l"(*reinterpret_cast<unsigned long long*>(&d))
        : "l"(*reinterpret_cast<unsigned long long*>(&a)),
          "l"(*reinterpret_cast<unsigned long long*>(&b)),
          "l"(*reinterpret_cast<unsigned long long*>(&c)));
    return d;
}
__device__ __forceinline__ float2 splat2(float v) { return make_float2(v, v); }

// Pair features for one row -> sFT column (threads 0..127 call this)
__device__ __forceinline__ void compute_feats(const float4* __restrict__ boxes4,
                                              int tile, int t, float* __restrict__ sFT)
{
    const int r = tile * TM + t;
    const int i = r / ROWS_I;
    const int p = r - i * ROWS_I;
    const int j = (p < i) ? p : p + 1;

    const float4 bi = boxes4[i];
    const float4 bj = boxes4[j];
    const float xi = bi.x, yi = bi.y, wi = bi.z, hi = bi.w;
    const float xj = bj.x, yj = bj.y, wj = bj.z, hj = bj.w;

    const float dx = __fdividef(xj - xi, wi);
    const float dy = __fdividef(yj - yi, hi);
    const float dw = __logf(__fdividef(wj, wi) + 1e-6f);
    const float dh = __logf(__fdividef(hj, hi) + 1e-6f);
    const float iw = fmaxf(0.0f, fminf(xi + wi, xj + wj) - fmaxf(xi, xj));
    const float ih = fmaxf(0.0f, fminf(yi + hi, yj + hj) - fmaxf(yi, yj));
    const float inter = iw * ih;
    const float uni = wi * hi + wj * hj - inter;
    const float iou = __fdividef(inter, uni + 1e-6f);

    sFT[0*128 + t] = dx;  sFT[1*128 + t] = dy;  sFT[2*128 + t] = dw;
    sFT[3*128 + t] = dh;  sFT[4*128 + t] = wi;  sFT[5*128 + t] = hi;
    sFT[6*128 + t] = wj;  sFT[7*128 + t] = hj;  sFT[8*128 + t] = iou;
    sFT[9*128 + t] = xi;  sFT[10*128 + t] = yi; sFT[11*128 + t] = xj;
    sFT[12*128 + t] = yj;
}

__global__ void __launch_bounds__(NTHREADS, 1)
pair_mlp_kernel(const float* __restrict__ boxes,
                const float* __restrict__ W1,
                const float* __restrict__ b1,
                const float* __restrict__ W2,
                const float* __restrict__ b2,
                float* __restrict__ out)
{
    extern __shared__ float smem[];
    float* sW2 = smem + OFF_W2;
    float* sHT = smem + OFF_HT;   // transposed h: sHT[n * S_H + m]
    float* sFT = smem + OFF_FT;   // sFT[kk * 128 + m]
    float* sW1 = smem + OFF_W1;   // row-major [13][128]

    const int t   = threadIdx.x;
    const int lid = t & 31;
    const int wid = t >> 5;
    const float4* boxes4 = reinterpret_cast<const float4*>(boxes);

    // ---- one-time staging: W2, W1 into smem ----
    #pragma unroll
    for (int i = 0; i < 16; i++)
        reinterpret_cast<float4*>(sW2)[t + i * NTHREADS] =
            reinterpret_cast<const float4*>(W2)[t + i * NTHREADS];
    #pragma unroll
    for (int i = t; i < 13 * 128; i += NTHREADS)
        sW1[i] = W1[i];

    // ---- hoisted biases (constant across tiles) ----
    // GEMM1: warp wid covers n in [16*wid, 16*wid+16): b1 for its 4 chunks.
    float4 b1r[4];
    #pragma unroll
    for (int nc = 0; nc < 4; nc++)
        b1r[nc] = *reinterpret_cast<const float4*>(b1 + wid * 16 + nc * 4);
    // GEMM2 epilogue: lane covers n0..n0+3 of output.
    const int n0 = lid * 4;
    const int m0 = wid * 16;
    const float4 b2r = *reinterpret_cast<const float4*>(b2 + n0);

    // feats for the first tile
    if (t < TM) compute_feats(boxes4, blockIdx.x, t, sFT);
    __syncthreads();

    for (int tile = blockIdx.x; tile < NTILES; tile += GRID) {
        // ================= Phase A: GEMM1 (packed) + relu -> sHT =================
        // warp -> 16 n-rows of sHT; lane -> m-pairs {2l, 2l+1} and {2l+64, 2l+65}.
        {
            const int ma = 2 * lid;
            const int mb = 2 * lid + 64;
            float2 fa[13], fb[13];
            #pragma unroll
            for (int kk = 0; kk < 13; kk++) {
                fa[kk] = *reinterpret_cast<const float2*>(&sFT[kk * 128 + ma]);
                fb[kk] = *reinterpret_cast<const float2*>(&sFT[kk * 128 + mb]);
            }
            #pragma unroll
            for (int nc = 0; nc < 4; nc++) {
                const int nb = wid * 16 + nc * 4;
                const float4 bv = b1r[nc];
                float2 aA0 = splat2(bv.x), aA1 = splat2(bv.y), aA2 = splat2(bv.z), aA3 = splat2(bv.w);
                float2 aB0 = aA0, aB1 = aA1, aB2 = aA2, aB3 = aA3;
                #pragma unroll
                for (int kk = 0; kk < 13; kk++) {
                    const float4 wv = *reinterpret_cast<const float4*>(&sW1[kk * 128 + nb]);
                    aA0 = ffma2(fa[kk], splat2(wv.x), aA0);
                    aB0 = ffma2(fb[kk], splat2(wv.x), aB0);
                    aA1 = ffma2(fa[kk], splat2(wv.y), aA1);
                    aB1 = ffma2(fb[kk], splat2(wv.y), aB1);
                    aA2 = ffma2(fa[kk], splat2(wv.z), aA2);
                    aB2 = ffma2(fb[kk], splat2(wv.z), aB2);
                    aA3 = ffma2(fa[kk], splat2(wv.w), aA3);
                    aB3 = ffma2(fb[kk], splat2(wv.w), aB3);
                }
                float2 rA, rB;
                rA.x = fmaxf(aA0.x, 0.f); rA.y = fmaxf(aA0.y, 0.f);
                rB.x = fmaxf(aB0.x, 0.f); rB.y = fmaxf(aB0.y, 0.f);
                *reinterpret_cast<float2*>(&sHT[(nb + 0) * S_H + ma]) = rA;
                *reinterpret_cast<float2*>(&sHT[(nb + 0) * S_H + mb]) = rB;
                rA.x = fmaxf(aA1.x, 0.f); rA.y = fmaxf(aA1.y, 0.f);
                rB.x = fmaxf(aB1.x, 0.f); rB.y = fmaxf(aB1.y, 0.f);
                *reinterpret_cast<float2*>(&sHT[(nb + 1) * S_H + ma]) = rA;
                *reinterpret_cast<float2*>(&sHT[(nb + 1) * S_H + mb]) = rB;
                rA.x = fmaxf(aA2.x, 0.f); rA.y = fmaxf(aA2.y, 0.f);
                rB.x = fmaxf(aB2.x, 0.f); rB.y = fmaxf(aB2.y, 0.f);
                *reinterpret_cast<float2*>(&sHT[(nb + 2) * S_H + ma]) = rA;
                *reinterpret_cast<float2*>(&sHT[(nb + 2) * S_H + mb]) = rB;
                rA.x = fmaxf(aA3.x, 0.f); rA.y = fmaxf(aA3.y, 0.f);
                rB.x = fmaxf(aB3.x, 0.f); rB.y = fmaxf(aB3.y, 0.f);
                *reinterpret_cast<float2*>(&sHT[(nb + 3) * S_H + ma]) = rA;
                *reinterpret_cast<float2*>(&sHT[(nb + 3) * S_H + mb]) = rB;
            }
        }
        __syncthreads();

        // ================= Phase B: GEMM2 mainloop (packed f32x2) =================
        // Thread tile: 16 rows (8 f32x2 pairs, warp-mapped) x 4 cols (lane-mapped).
        float2 c[8][4];
        #pragma unroll
        for (int mi = 0; mi < 8; mi++) {
            c[mi][0] = splat2(b2r.x); c[mi][1] = splat2(b2r.y);
            c[mi][2] = splat2(b2r.z); c[mi][3] = splat2(b2r.w);
        }

        #pragma unroll 4
        for (int k = 0; k < 128; k++) {
            const float4 wv = *reinterpret_cast<const float4*>(&sW2[k * 128 + n0]);
            float2 a[8];
            const float* hrow = &sHT[k * S_H + m0];
            #pragma unroll
            for (int mi = 0; mi < 8; mi++)
                a[mi] = *reinterpret_cast<const float2*>(hrow + 2 * mi); // warp broadcast

            const float2 w0 = splat2(wv.x), w1v = splat2(wv.y);
            const float2 w2v = splat2(wv.z), w3 = splat2(wv.w);
            #pragma unroll
            for (int mi = 0; mi < 8; mi++) {
                c[mi][0] = ffma2(a[mi], w0,  c[mi][0]);
                c[mi][1] = ffma2(a[mi], w1v, c[mi][1]);
                c[mi][2] = ffma2(a[mi], w2v, c[mi][2]);
                c[mi][3] = ffma2(a[mi], w3,  c[mi][3]);
            }
        }

        // ---- epilogue: coalesced STG.128 ----
        float* outBase = out + ((size_t)tile * TM + m0) * 128 + n0;
        #pragma unroll
        for (int mi = 0; mi < 8; mi++) {
            const float4 r0 = make_float4(c[mi][0].x, c[mi][1].x, c[mi][2].x, c[mi][3].x);
            const float4 r1 = make_float4(c[mi][0].y, c[mi][1].y, c[mi][2].y, c[mi][3].y);
            *reinterpret_cast<float4*>(outBase + (size_t)(2 * mi) * 128)     = r0;
            *reinterpret_cast<float4*>(outBase + (size_t)(2 * mi + 1) * 128) = r1;
        }

        // ---- feats for the next tile (sFT unused during phase B) ----
        const int next = tile + GRID;
        if (next < NTILES && t < TM) compute_feats(boxes4, next, t, sFT);
        __syncthreads();
    }
}

extern "C" void kernel_launch(void* const* d_in, const int* in_sizes, int n_in,
                              void* d_out, int out_size)
{
    const float* boxes = (const float*)d_in[0];
    const float* W1    = (const float*)d_in[1];
    const float* b1    = (const float*)d_in[2];
    const float* W2    = (const float*)d_in[3];
    const float* b2    = (const float*)d_in[4];
    float* out = (float*)d_out;

    cudaFuncSetAttribute(pair_mlp_kernel,
                         cudaFuncAttributeMaxDynamicSharedMemorySize, SMEM_BYTES);

    pair_mlp_kernel<<<GRID, NTHREADS, SMEM_BYTES>>>(boxes, W1, b1, W2, b2, out);
}